// round 12
// baseline (speedup 1.0000x reference)
#include <cuda_runtime.h>
#include <math.h>

#define Bdim 2
#define Ldim 32
#define Edim 256
#define Hdim 4096
#define Gdim 16
#define Rdim 64

// ---------------- device scratch (no allocations allowed) ----------------
__device__ __align__(16) float g_wkq[Hdim];            // Wk^T @ layer_query
__device__ __align__(16) float g_WkT[Hdim * Rdim];     // Wk transposed [H,R]
__device__ __align__(16) float g_WvT[Hdim * Rdim];     // Wv transposed [H,R]
__device__ float g_scores[Bdim * Ldim];                // layer logits (pre-scale)
__device__ float g_w[Bdim * Ldim];                     // layer softmax weights
__device__ __align__(16) float g_k[Bdim * Edim * Rdim];// projected k [B,E,R]
__device__ __align__(16) float g_v[Bdim * Edim * Rdim];// projected v [B,E,R]
__device__ __align__(16) float g_q[Gdim * Rdim];       // global_q @ Wq^T

// ---------------- kernel 0: prep (q GEMV blocks + transpose/zero/wkq) ----
// blocks [0, G*R): one block per (g,r) output of q = global_q @ Wq^T
// blocks [G*R, G*R + H*R/256): transpose Wk/Wv, compute wkq, zero accumulators
__global__ void k_prep(const float* __restrict__ Wq, const float* __restrict__ Wk,
                       const float* __restrict__ Wv, const float* __restrict__ gq,
                       const float* __restrict__ lq) {
    int tid = threadIdx.x;
    __shared__ float red[256];
    if (blockIdx.x < Gdim * Rdim) {
        int g = blockIdx.x >> 6;      // /Rdim
        int r = blockIdx.x & (Rdim - 1);
        const float* a = gq + (size_t)g * Hdim;
        const float* w = Wq + (size_t)r * Hdim;
        float acc = 0.f;
        for (int i = tid; i < Hdim; i += 256) acc += a[i] * w[i];
        red[tid] = acc;
        __syncthreads();
        for (int s = 128; s > 0; s >>= 1) {
            if (tid < s) red[tid] += red[tid + s];
            __syncthreads();
        }
        if (tid == 0) g_q[blockIdx.x] = red[0];
    } else {
        int gid = (blockIdx.x - Gdim * Rdim) * 256 + tid;   // [0, H*R)
        int r = gid >> 12;            // /Hdim
        int h = gid & (Hdim - 1);
        g_WkT[h * Rdim + r] = Wk[gid];
        g_WvT[h * Rdim + r] = Wv[gid];
        if (gid < Hdim) {
            float acc = 0.f;
#pragma unroll
            for (int rr = 0; rr < Rdim; rr++) acc += Wk[rr * Hdim + gid] * lq[rr];
            g_wkq[gid] = acc;
        }
        if (gid < Bdim * Edim * Rdim) { g_k[gid] = 0.f; g_v[gid] = 0.f; }
        if (gid < Bdim * Ldim) g_scores[gid] = 0.f;
    }
}

// ---------------- kernel 1: layer logits: sum_{e,h} K * wkq ---------------
// grid = (B*L) * 32 chunk-blocks; one full read of K (268 MB), memory-bound.
__global__ void k_layer_scores(const float4* __restrict__ K4) {
    int pair = blockIdx.x >> 5;                 // (b*L + l)
    int chunk = blockIdx.x & 31;
    const int PER = (Edim * Hdim / 4) / 32;     // 8192 float4 per chunk
    size_t base = (size_t)pair * (Edim * Hdim / 4) + (size_t)chunk * PER;
    const float4* wq4 = (const float4*)g_wkq;   // 1024 float4, row-periodic
    float acc = 0.f;
    for (int j = threadIdx.x; j < PER; j += 256) {
        float4 kv = K4[base + j];
        float4 w = wq4[j & 1023];               // h position within H row
        acc += kv.x * w.x + kv.y * w.y + kv.z * w.z + kv.w * w.w;
    }
    __shared__ float red[256];
    red[threadIdx.x] = acc;
    __syncthreads();
    for (int s = 128; s > 0; s >>= 1) {
        if (threadIdx.x < s) red[threadIdx.x] += red[threadIdx.x + s];
        __syncthreads();
    }
    if (threadIdx.x == 0) atomicAdd(&g_scores[pair], red[0]);
}

// ---------------- kernel 2: softmax over layers (tiny) --------------------
__global__ void k_layer_softmax() {
    int b = threadIdx.x >> 5;
    int l = threadIdx.x & 31;
    float s = g_scores[b * Ldim + l] * (1.0f / Edim) * 0.125f;  // mean_E, 1/sqrt(R)
    float m = s;
#pragma unroll
    for (int o = 16; o; o >>= 1) m = fmaxf(m, __shfl_xor_sync(0xffffffffu, m, o));
    float e = expf(s - m);
    float sum = e;
#pragma unroll
    for (int o = 16; o; o >>= 1) sum += __shfl_xor_sync(0xffffffffu, sum, o);
    g_w[b * Ldim + l] = e / sum;
}

// ---------------- kernel 3: layer-weighted sum + low-rank projection ------
// block = (b, e-tile of 16, h-chunk of 256). Phase 1: ek/ev tile in SMEM
// (reads K+V once, 536 MB). Phase 2: project tile against WkT/WvT chunk,
// atomicAdd partial k/v[B,E,R].
__global__ void k_wproj(const float4* __restrict__ K4, const float4* __restrict__ V4) {
    const int ET = 16, HC = 256;
    int b  = blockIdx.x >> 8;
    int et = (blockIdx.x >> 4) & 15;
    int hc = blockIdx.x & 15;
    int e0 = et * ET;
    int h0 = hc * HC;
    int tid = threadIdx.x;

    __shared__ float w_s[Ldim];
    __shared__ float ek[ET][HC];
    __shared__ float ev[ET][HC];
    if (tid < Ldim) w_s[tid] = g_w[b * Ldim + tid];
    __syncthreads();

    const size_t lstride = (size_t)Edim * (Hdim / 4);
#pragma unroll
    for (int i = 0; i < 4; i++) {
        int p = tid + 256 * i;            // 0..1023 float4 positions
        int e_loc = p >> 6;               // 64 float4 per e row-chunk
        int h4 = p & 63;
        size_t idx = ((size_t)b * Ldim * Edim + (size_t)(e0 + e_loc)) * (Hdim / 4)
                     + (h0 >> 2) + h4;
        float4 ak = make_float4(0.f, 0.f, 0.f, 0.f);
        float4 av = make_float4(0.f, 0.f, 0.f, 0.f);
#pragma unroll 4
        for (int l = 0; l < Ldim; l++) {
            float wl = w_s[l];
            float4 kk = K4[idx + (size_t)l * lstride];
            float4 vv = V4[idx + (size_t)l * lstride];
            ak.x += wl * kk.x; ak.y += wl * kk.y; ak.z += wl * kk.z; ak.w += wl * kk.w;
            av.x += wl * vv.x; av.y += wl * vv.y; av.z += wl * vv.z; av.w += wl * vv.w;
        }
        *(float4*)&ek[e_loc][h4 << 2] = ak;
        *(float4*)&ev[e_loc][h4 << 2] = av;
    }
    __syncthreads();

    // Phase 2: thread = (e_loc = tid/16, rq = tid%16 -> 4 consecutive r)
    int e_loc = tid >> 4;
    int rq = tid & 15;
    const float4* WkT4 = (const float4*)g_WkT;
    const float4* WvT4 = (const float4*)g_WvT;
    float4 ack = make_float4(0.f, 0.f, 0.f, 0.f);
    float4 acv = make_float4(0.f, 0.f, 0.f, 0.f);
    for (int h = 0; h < HC; h++) {
        float a = ek[e_loc][h];
        float c = ev[e_loc][h];
        float4 wk = WkT4[(size_t)(h0 + h) * 16 + rq];
        float4 wv = WvT4[(size_t)(h0 + h) * 16 + rq];
        ack.x += a * wk.x; ack.y += a * wk.y; ack.z += a * wk.z; ack.w += a * wk.w;
        acv.x += c * wv.x; acv.y += c * wv.y; acv.z += c * wv.z; acv.w += c * wv.w;
    }
    float* dk = &g_k[((size_t)b * Edim + e0 + e_loc) * Rdim + (rq << 2)];
    float* dv = &g_v[((size_t)b * Edim + e0 + e_loc) * Rdim + (rq << 2)];
    atomicAdd(dk + 0, ack.x); atomicAdd(dk + 1, ack.y);
    atomicAdd(dk + 2, ack.z); atomicAdd(dk + 3, ack.w);
    atomicAdd(dv + 0, acv.x); atomicAdd(dv + 1, acv.y);
    atomicAdd(dv + 2, acv.z); atomicAdd(dv + 3, acv.w);
}

// ---------------- kernel 4: cross-attn, gate, state update (tiny) ---------
__global__ void k_final(const float* __restrict__ state, const int* __restrict__ etpl,
                        float* __restrict__ out) {
    int b = blockIdx.x;
    int tid = threadIdx.x;
    __shared__ float q_s[Gdim * Rdim];
    __shared__ float sc[Gdim][Edim];
    __shared__ float ctx[Gdim][Rdim];
    __shared__ float rp[Rdim], rs[Rdim], rx[Rdim];
    __shared__ float gate_s, scale_s;

    for (int i = tid; i < Gdim * Rdim; i += 256) q_s[i] = g_q[i];
    __syncthreads();

    const float4* k4 = (const float4*)&g_k[(size_t)b * Edim * Rdim];
    const float4* v4 = (const float4*)&g_v[(size_t)b * Edim * Rdim];

    // scores[g][e] = q[g,:] . k[e,:] * 1/sqrt(R)
    for (int i = 0; i < 16; i++) {
        int p = tid + 256 * i;           // 4096 (g,e) pairs
        int g = p >> 8;
        int e = p & 255;
        const float4* qq = (const float4*)&q_s[g * Rdim];
        float acc = 0.f;
#pragma unroll
        for (int r4 = 0; r4 < 16; r4++) {
            float4 a = qq[r4];
            float4 c = k4[e * 16 + r4];
            acc += a.x * c.x + a.y * c.y + a.z * c.z + a.w * c.w;
        }
        sc[g][e] = acc * 0.125f;
    }
    __syncthreads();

    // softmax over e, each warp handles 2 g's
    int warp = tid >> 5, lane = tid & 31;
    for (int j = 0; j < 2; j++) {
        int g = warp * 2 + j;
        float m = -1e30f;
        for (int e = lane; e < Edim; e += 32) m = fmaxf(m, sc[g][e]);
#pragma unroll
        for (int o = 16; o; o >>= 1) m = fmaxf(m, __shfl_xor_sync(0xffffffffu, m, o));
        float sum = 0.f;
        for (int e = lane; e < Edim; e += 32) {
            float ex = expf(sc[g][e] - m);
            sc[g][e] = ex;
            sum += ex;
        }
#pragma unroll
        for (int o = 16; o; o >>= 1) sum += __shfl_xor_sync(0xffffffffu, sum, o);
        float inv = 1.0f / sum;
        for (int e = lane; e < Edim; e += 32) sc[g][e] *= inv;
    }
    __syncthreads();

    // context[g][r] = attn[g,:] @ v[:,r]
    {
        int g = tid >> 4;
        int rq = tid & 15;
        float4 acc = make_float4(0.f, 0.f, 0.f, 0.f);
        for (int e = 0; e < Edim; e++) {
            float a = sc[g][e];
            float4 vv = v4[e * 16 + rq];
            acc.x += a * vv.x; acc.y += a * vv.y; acc.z += a * vv.z; acc.w += a * vv.w;
        }
        *(float4*)&ctx[g][rq << 2] = acc;
    }
    __syncthreads();

    // s_new = mean over g; gated update; norm clamp
    float snew = 0.f, prev = 0.f, u = 0.f;
    if (tid < Rdim) {
#pragma unroll
        for (int g = 0; g < Gdim; g++) snew += ctx[g][tid];
        snew *= (1.0f / Gdim);
        prev = state[b * Rdim + tid];
        rp[tid] = prev * prev;
        rs[tid] = snew * snew;
        rx[tid] = prev * snew;
    }
    __syncthreads();
    if (tid == 0) {
        float pp = 0.f, ss = 0.f, xx = 0.f;
        for (int i = 0; i < Rdim; i++) { pp += rp[i]; ss += rs[i]; xx += rx[i]; }
        float np = fmaxf(sqrtf(pp), 1e-6f);
        float ns = fmaxf(sqrtf(ss), 1e-6f);
        float sim = xx / (np * ns);
        sim = fminf(1.0f, fmaxf(-1.0f, sim));
        float gate = 0.1f + (0.9f - 0.1f) * 0.5f * (sim + 1.0f);
        // evicted_tokens_per_layer: int32 expected; hedge against float32 encoding
        int raw = *etpl;
        float tokens = (raw > 0 && raw < (1 << 24)) ? (float)raw : __int_as_float(raw);
        float evidence = fminf(1.0f, tokens / 256.0f);
        gate_s = gate * evidence;
    }
    __syncthreads();
    if (tid < Rdim) {
        u = (1.0f - gate_s) * prev + gate_s * snew;
        rp[tid] = u * u;
    }
    __syncthreads();
    if (tid == 0) {
        float nn = 0.f;
        for (int i = 0; i < Rdim; i++) nn += rp[i];
        float n = fmaxf(sqrtf(nn), 1e-6f);
        scale_s = fminf(1.0f, 10.0f / n);
    }
    __syncthreads();
    if (tid < Rdim) out[b * Rdim + tid] = u * scale_s;
}

// ---------------- launch ----------------
extern "C" void kernel_launch(void* const* d_in, const int* in_sizes, int n_in,
                              void* d_out, int out_size) {
    const float* state = (const float*)d_in[0];
    const float* K     = (const float*)d_in[1];
    const float* V     = (const float*)d_in[2];
    const float* Wq    = (const float*)d_in[3];
    const float* Wk    = (const float*)d_in[4];
    const float* Wv    = (const float*)d_in[5];
    const float* gq    = (const float*)d_in[6];
    const float* lq    = (const float*)d_in[7];
    const int*   etpl  = (const int*)d_in[8];
    float* out = (float*)d_out;

    k_prep<<<Gdim * Rdim + (Hdim * Rdim) / 256, 256>>>(Wq, Wk, Wv, gq, lq);
    k_layer_scores<<<Bdim * Ldim * 32, 256>>>((const float4*)K);
    k_layer_softmax<<<1, 64>>>();
    k_wproj<<<Bdim * 16 * 16, 256>>>((const float4*)K, (const float4*)V);
    k_final<<<Bdim, 256>>>(state, etpl, out);
}

// round 16
// speedup vs baseline: 1.0029x; 1.0029x over previous
#include <cuda_runtime.h>
#include <math.h>

#define Bdim 2
#define Ldim 32
#define Edim 256
#define Hdim 4096
#define Gdim 16
#define Rdim 64

// ---------------- device scratch (no allocations allowed) ----------------
__device__ __align__(16) float g_wkq[Hdim];            // Wk^T @ layer_query
__device__ __align__(16) float g_WkT[Hdim * Rdim];     // Wk transposed [H,R]
__device__ __align__(16) float g_WvT[Hdim * Rdim];     // Wv transposed [H,R]
__device__ float g_scores[Bdim * Ldim];                // layer logits (pre-scale)
__device__ float g_w[Bdim * Ldim];                     // layer softmax weights
__device__ __align__(16) float g_k[Bdim * Edim * Rdim];// projected k [B,E,R]
__device__ __align__(16) float g_v[Bdim * Edim * Rdim];// projected v [B,E,R]
__device__ __align__(16) float g_q[Gdim * Rdim];       // global_q @ Wq^T

// ---------------- kernel 0: prep (q GEMV blocks + transpose/zero/wkq) ----
// blocks [0, G*R): one block per (g,r) output of q = global_q @ Wq^T
// blocks [G*R, G*R + H*R/256): transpose Wk/Wv, compute wkq, zero accumulators
__global__ void k_prep(const float* __restrict__ Wq, const float* __restrict__ Wk,
                       const float* __restrict__ Wv, const float* __restrict__ gq,
                       const float* __restrict__ lq) {
    int tid = threadIdx.x;
    __shared__ float red[256];
    if (blockIdx.x < Gdim * Rdim) {
        int g = blockIdx.x >> 6;      // /Rdim
        int r = blockIdx.x & (Rdim - 1);
        const float* a = gq + (size_t)g * Hdim;
        const float* w = Wq + (size_t)r * Hdim;
        float acc = 0.f;
        for (int i = tid; i < Hdim; i += 256) acc += a[i] * w[i];
        red[tid] = acc;
        __syncthreads();
        for (int s = 128; s > 0; s >>= 1) {
            if (tid < s) red[tid] += red[tid + s];
            __syncthreads();
        }
        if (tid == 0) g_q[blockIdx.x] = red[0];
    } else {
        int gid = (blockIdx.x - Gdim * Rdim) * 256 + tid;   // [0, H*R)
        int r = gid >> 12;            // /Hdim
        int h = gid & (Hdim - 1);
        g_WkT[h * Rdim + r] = Wk[gid];
        g_WvT[h * Rdim + r] = Wv[gid];
        if (gid < Hdim) {
            float acc = 0.f;
#pragma unroll
            for (int rr = 0; rr < Rdim; rr++) acc += Wk[rr * Hdim + gid] * lq[rr];
            g_wkq[gid] = acc;
        }
        if (gid < Bdim * Edim * Rdim) { g_k[gid] = 0.f; g_v[gid] = 0.f; }
        if (gid < Bdim * Ldim) g_scores[gid] = 0.f;
    }
}

// ---------------- kernel 1: layer logits: sum_{e,h} K * wkq ---------------
// grid = (B*L) * 32 chunk-blocks; one full read of K (268 MB), memory-bound.
__global__ void k_layer_scores(const float4* __restrict__ K4) {
    int pair = blockIdx.x >> 5;                 // (b*L + l)
    int chunk = blockIdx.x & 31;
    const int PER = (Edim * Hdim / 4) / 32;     // 8192 float4 per chunk
    size_t base = (size_t)pair * (Edim * Hdim / 4) + (size_t)chunk * PER;
    const float4* wq4 = (const float4*)g_wkq;   // 1024 float4, row-periodic
    float acc = 0.f;
    for (int j = threadIdx.x; j < PER; j += 256) {
        float4 kv = K4[base + j];
        float4 w = wq4[j & 1023];               // h position within H row
        acc += kv.x * w.x + kv.y * w.y + kv.z * w.z + kv.w * w.w;
    }
    __shared__ float red[256];
    red[threadIdx.x] = acc;
    __syncthreads();
    for (int s = 128; s > 0; s >>= 1) {
        if (threadIdx.x < s) red[threadIdx.x] += red[threadIdx.x + s];
        __syncthreads();
    }
    if (threadIdx.x == 0) atomicAdd(&g_scores[pair], red[0]);
}

// ---------------- kernel 2: softmax over layers (tiny) --------------------
__global__ void k_layer_softmax() {
    int b = threadIdx.x >> 5;
    int l = threadIdx.x & 31;
    float s = g_scores[b * Ldim + l] * (1.0f / Edim) * 0.125f;  // mean_E, 1/sqrt(R)
    float m = s;
#pragma unroll
    for (int o = 16; o; o >>= 1) m = fmaxf(m, __shfl_xor_sync(0xffffffffu, m, o));
    float e = expf(s - m);
    float sum = e;
#pragma unroll
    for (int o = 16; o; o >>= 1) sum += __shfl_xor_sync(0xffffffffu, sum, o);
    g_w[b * Ldim + l] = e / sum;
}

// ---------------- kernel 3: layer-weighted sum + low-rank projection ------
// block = (b, e-tile of 16, h-chunk of 256). Phase 1: ek/ev tile in SMEM
// (reads K+V once, 536 MB). Phase 2: project tile against WkT/WvT chunk,
// atomicAdd partial k/v[B,E,R].
__global__ void k_wproj(const float4* __restrict__ K4, const float4* __restrict__ V4) {
    const int ET = 16, HC = 256;
    int b  = blockIdx.x >> 8;
    int et = (blockIdx.x >> 4) & 15;
    int hc = blockIdx.x & 15;
    int e0 = et * ET;
    int h0 = hc * HC;
    int tid = threadIdx.x;

    __shared__ float w_s[Ldim];
    __shared__ float ek[ET][HC];
    __shared__ float ev[ET][HC];
    if (tid < Ldim) w_s[tid] = g_w[b * Ldim + tid];
    __syncthreads();

    const size_t lstride = (size_t)Edim * (Hdim / 4);
#pragma unroll
    for (int i = 0; i < 4; i++) {
        int p = tid + 256 * i;            // 0..1023 float4 positions
        int e_loc = p >> 6;               // 64 float4 per e row-chunk
        int h4 = p & 63;
        size_t idx = ((size_t)b * Ldim * Edim + (size_t)(e0 + e_loc)) * (Hdim / 4)
                     + (h0 >> 2) + h4;
        float4 ak = make_float4(0.f, 0.f, 0.f, 0.f);
        float4 av = make_float4(0.f, 0.f, 0.f, 0.f);
#pragma unroll 4
        for (int l = 0; l < Ldim; l++) {
            float wl = w_s[l];
            float4 kk = K4[idx + (size_t)l * lstride];
            float4 vv = V4[idx + (size_t)l * lstride];
            ak.x += wl * kk.x; ak.y += wl * kk.y; ak.z += wl * kk.z; ak.w += wl * kk.w;
            av.x += wl * vv.x; av.y += wl * vv.y; av.z += wl * vv.z; av.w += wl * vv.w;
        }
        *(float4*)&ek[e_loc][h4 << 2] = ak;
        *(float4*)&ev[e_loc][h4 << 2] = av;
    }
    __syncthreads();

    // Phase 2: thread = (e_loc = tid/16, rq = tid%16 -> 4 consecutive r)
    int e_loc = tid >> 4;
    int rq = tid & 15;
    const float4* WkT4 = (const float4*)g_WkT;
    const float4* WvT4 = (const float4*)g_WvT;
    float4 ack = make_float4(0.f, 0.f, 0.f, 0.f);
    float4 acv = make_float4(0.f, 0.f, 0.f, 0.f);
    for (int h = 0; h < HC; h++) {
        float a = ek[e_loc][h];
        float c = ev[e_loc][h];
        float4 wk = WkT4[(size_t)(h0 + h) * 16 + rq];
        float4 wv = WvT4[(size_t)(h0 + h) * 16 + rq];
        ack.x += a * wk.x; ack.y += a * wk.y; ack.z += a * wk.z; ack.w += a * wk.w;
        acv.x += c * wv.x; acv.y += c * wv.y; acv.z += c * wv.z; acv.w += c * wv.w;
    }
    float* dk = &g_k[((size_t)b * Edim + e0 + e_loc) * Rdim + (rq << 2)];
    float* dv = &g_v[((size_t)b * Edim + e0 + e_loc) * Rdim + (rq << 2)];
    atomicAdd(dk + 0, ack.x); atomicAdd(dk + 1, ack.y);
    atomicAdd(dk + 2, ack.z); atomicAdd(dk + 3, ack.w);
    atomicAdd(dv + 0, acv.x); atomicAdd(dv + 1, acv.y);
    atomicAdd(dv + 2, acv.z); atomicAdd(dv + 3, acv.w);
}

// ---------------- kernel 4: cross-attn, gate, state update (tiny) ---------
__global__ void k_final(const float* __restrict__ state, const int* __restrict__ etpl,
                        float* __restrict__ out) {
    int b = blockIdx.x;
    int tid = threadIdx.x;
    __shared__ float q_s[Gdim * Rdim];
    __shared__ float sc[Gdim][Edim];
    __shared__ float ctx[Gdim][Rdim];
    __shared__ float rp[Rdim], rs[Rdim], rx[Rdim];
    __shared__ float gate_s, scale_s;

    for (int i = tid; i < Gdim * Rdim; i += 256) q_s[i] = g_q[i];
    __syncthreads();

    const float4* k4 = (const float4*)&g_k[(size_t)b * Edim * Rdim];
    const float4* v4 = (const float4*)&g_v[(size_t)b * Edim * Rdim];

    // scores[g][e] = q[g,:] . k[e,:] * 1/sqrt(R)
    for (int i = 0; i < 16; i++) {
        int p = tid + 256 * i;           // 4096 (g,e) pairs
        int g = p >> 8;
        int e = p & 255;
        const float4* qq = (const float4*)&q_s[g * Rdim];
        float acc = 0.f;
#pragma unroll
        for (int r4 = 0; r4 < 16; r4++) {
            float4 a = qq[r4];
            float4 c = k4[e * 16 + r4];
            acc += a.x * c.x + a.y * c.y + a.z * c.z + a.w * c.w;
        }
        sc[g][e] = acc * 0.125f;
    }
    __syncthreads();

    // softmax over e, each warp handles 2 g's
    int warp = tid >> 5, lane = tid & 31;
    for (int j = 0; j < 2; j++) {
        int g = warp * 2 + j;
        float m = -1e30f;
        for (int e = lane; e < Edim; e += 32) m = fmaxf(m, sc[g][e]);
#pragma unroll
        for (int o = 16; o; o >>= 1) m = fmaxf(m, __shfl_xor_sync(0xffffffffu, m, o));
        float sum = 0.f;
        for (int e = lane; e < Edim; e += 32) {
            float ex = expf(sc[g][e] - m);
            sc[g][e] = ex;
            sum += ex;
        }
#pragma unroll
        for (int o = 16; o; o >>= 1) sum += __shfl_xor_sync(0xffffffffu, sum, o);
        float inv = 1.0f / sum;
        for (int e = lane; e < Edim; e += 32) sc[g][e] *= inv;
    }
    __syncthreads();

    // context[g][r] = attn[g,:] @ v[:,r]
    {
        int g = tid >> 4;
        int rq = tid & 15;
        float4 acc = make_float4(0.f, 0.f, 0.f, 0.f);
        for (int e = 0; e < Edim; e++) {
            float a = sc[g][e];
            float4 vv = v4[e * 16 + rq];
            acc.x += a * vv.x; acc.y += a * vv.y; acc.z += a * vv.z; acc.w += a * vv.w;
        }
        *(float4*)&ctx[g][rq << 2] = acc;
    }
    __syncthreads();

    // s_new = mean over g; gated update; norm clamp
    float snew = 0.f, prev = 0.f, u = 0.f;
    if (tid < Rdim) {
#pragma unroll
        for (int g = 0; g < Gdim; g++) snew += ctx[g][tid];
        snew *= (1.0f / Gdim);
        prev = state[b * Rdim + tid];
        rp[tid] = prev * prev;
        rs[tid] = snew * snew;
        rx[tid] = prev * snew;
    }
    __syncthreads();
    if (tid == 0) {
        float pp = 0.f, ss = 0.f, xx = 0.f;
        for (int i = 0; i < Rdim; i++) { pp += rp[i]; ss += rs[i]; xx += rx[i]; }
        float np = fmaxf(sqrtf(pp), 1e-6f);
        float ns = fmaxf(sqrtf(ss), 1e-6f);
        float sim = xx / (np * ns);
        sim = fminf(1.0f, fmaxf(-1.0f, sim));
        float gate = 0.1f + (0.9f - 0.1f) * 0.5f * (sim + 1.0f);
        // evicted_tokens_per_layer: int32 expected; hedge against float32 encoding
        int raw = *etpl;
        float tokens = (raw > 0 && raw < (1 << 24)) ? (float)raw : __int_as_float(raw);
        float evidence = fminf(1.0f, tokens / 256.0f);
        gate_s = gate * evidence;
    }
    __syncthreads();
    if (tid < Rdim) {
        u = (1.0f - gate_s) * prev + gate_s * snew;
        rp[tid] = u * u;
    }
    __syncthreads();
    if (tid == 0) {
        float nn = 0.f;
        for (int i = 0; i < Rdim; i++) nn += rp[i];
        float n = fmaxf(sqrtf(nn), 1e-6f);
        scale_s = fminf(1.0f, 10.0f / n);
    }
    __syncthreads();
    if (tid < Rdim) out[b * Rdim + tid] = u * scale_s;
}

// ---------------- launch ----------------
extern "C" void kernel_launch(void* const* d_in, const int* in_sizes, int n_in,
                              void* d_out, int out_size) {
    const float* state = (const float*)d_in[0];
    const float* K     = (const float*)d_in[1];
    const float* V     = (const float*)d_in[2];
    const float* Wq    = (const float*)d_in[3];
    const float* Wk    = (const float*)d_in[4];
    const float* Wv    = (const float*)d_in[5];
    const float* gq    = (const float*)d_in[6];
    const float* lq    = (const float*)d_in[7];
    const int*   etpl  = (const int*)d_in[8];
    float* out = (float*)d_out;

    k_prep<<<Gdim * Rdim + (Hdim * Rdim) / 256, 256>>>(Wq, Wk, Wv, gq, lq);
    k_layer_scores<<<Bdim * Ldim * 32, 256>>>((const float4*)K);
    k_layer_softmax<<<1, 64>>>();
    k_wproj<<<Bdim * 16 * 16, 256>>>((const float4*)K, (const float4*)V);
    k_final<<<Bdim, 256>>>(state, etpl, out);
}